// round 5
// baseline (speedup 1.0000x reference)
#include <cuda_runtime.h>
#include <cuda_bf16.h>
#include <math.h>
#include <stdint.h>

constexpr int Bb = 4;
constexpr int Np = 20000;
constexpr int Cc = 256;
constexpr int NS = 1024;
constexpr int NV = 300;

// output offsets (float32 elements), reference return order, row-major flatten
constexpr size_t OFF0 = 0;        // objectness (B,2,N)
constexpr size_t OFF1 = 160000;   // graspness (B,N)
constexpr size_t OFF2 = 240000;   // graspable_xyz (B,NS,3)
constexpr size_t OFF3 = 252288;   // graspable_inds (B,NS)
constexpr size_t OFF4 = 256384;   // graspable_features (B,C,NS)
constexpr size_t OFF5 = 1304960;  // fp2_graspness (B,NS)
constexpr size_t OFF6 = 1309056;  // vp_xyz (B,NS,3)
constexpr size_t OFF7 = 1321344;  // top_view_inds (B,NS)
constexpr size_t OFF8 = 1325440;  // vp_rot (B,NS,3,3)

__device__ unsigned char g_mask[Bb * Np];
__device__ int    g_cidx[Bb][Np];
__device__ float4 g_cxyz[Bb][Np];
__device__ int    g_sel[Bb][NS];

// ---------- shared GEMM tile constants (64 points x 256 co per block) ----------
constexpr int TPTS = 64;
constexpr int SM_FSM = 0;        // 256 x 64 = 16384
constexpr int SM_WSM = 16384;    // 8 x 256  = 2048
constexpr int SM_W2  = 18432;    // 768
constexpr int SM_B2  = 19200;    // 4
constexpr int SM1_FLOATS = 19204;
constexpr int SM_VSM = 19204;    // 900
constexpr int SM_IDX = 20104;    // 64 ints
constexpr int SM_VPS = 20168;    // 192
constexpr int SM4_FLOATS = 20360;

__device__ __forceinline__ void gemm_tile(const float* __restrict__ W, float* sm,
                                          int tid, int tx, int ty, float acc[8][8]) {
    float* fsm = sm + SM_FSM;
    float* wsm = sm + SM_WSM;
    for (int ck = 0; ck < 32; ++ck) {
        {
            const float4* srcw = reinterpret_cast<const float4*>(W + tid * 256 + ck * 8);
            float4 a = srcw[0], b = srcw[1];
            wsm[0 * 256 + tid] = a.x; wsm[1 * 256 + tid] = a.y;
            wsm[2 * 256 + tid] = a.z; wsm[3 * 256 + tid] = a.w;
            wsm[4 * 256 + tid] = b.x; wsm[5 * 256 + tid] = b.y;
            wsm[6 * 256 + tid] = b.z; wsm[7 * 256 + tid] = b.w;
        }
        __syncthreads();
#pragma unroll
        for (int ci = 0; ci < 8; ++ci) {
            const float* wrow = wsm + ci * 256 + 8 * ty;
            float4 wa = *reinterpret_cast<const float4*>(wrow);
            float4 wb = *reinterpret_cast<const float4*>(wrow + 4);
            const float* frow = fsm + (ck * 8 + ci) * TPTS + 8 * tx;
            float4 fa = *reinterpret_cast<const float4*>(frow);
            float4 fb = *reinterpret_cast<const float4*>(frow + 4);
            float w[8] = {wa.x, wa.y, wa.z, wa.w, wb.x, wb.y, wb.z, wb.w};
            float f[8] = {fa.x, fa.y, fa.z, fa.w, fb.x, fb.y, fb.z, fb.w};
#pragma unroll
            for (int j = 0; j < 8; ++j)
#pragma unroll
                for (int p = 0; p < 8; ++p) acc[j][p] = fmaf(w[j], f[p], acc[j][p]);
        }
        __syncthreads();
    }
}

__device__ __forceinline__ void bn_params(const float* gg, const float* be, const float* mm,
                                          const float* vv, const float* b1, int ty,
                                          float sc[8], float bias2[8], float b1v[8]) {
#pragma unroll
    for (int j = 0; j < 8; ++j) {
        int co = 8 * ty + j;
        float s = __fdiv_rn(gg[co], sqrtf(__fadd_rn(vv[co], 1e-5f)));
        sc[j] = s;
        bias2[j] = __fsub_rn(be[co], __fmul_rn(mm[co], s));
        b1v[j] = b1[co];
    }
}

__device__ __forceinline__ void head3(const float* w2sm, float acc[8][8],
                                      const float sc[8], const float bias2[8],
                                      const float b1v[8], int ty, float p3[3][8]) {
#pragma unroll
    for (int j = 0; j < 8; ++j) {
        int co = 8 * ty + j;
        float w0 = w2sm[co], w1c = w2sm[256 + co], w2c = w2sm[512 + co];
#pragma unroll
        for (int p = 0; p < 8; ++p) {
            float t = __fadd_rn(acc[j][p], b1v[j]);
            t = __fmul_rn(t, sc[j]);
            t = __fadd_rn(t, bias2[j]);
            float h = fmaxf(t, 0.f);
            p3[0][p] = fmaf(w0, h, p3[0][p]);
            p3[1][p] = fmaf(w1c, h, p3[1][p]);
            p3[2][p] = fmaf(w2c, h, p3[2][p]);
        }
    }
}

__device__ __forceinline__ void reduce3(float* red, float p3[3][8], int tx, int ty) {
#pragma unroll
    for (int k = 0; k < 3; ++k)
#pragma unroll
        for (int p = 0; p < 8; ++p) red[ty * 192 + k * 64 + 8 * tx + p] = p3[k][p];
    __syncthreads();
    for (int s = 16; s >= 1; s >>= 1) {
        if (ty < s) {
#pragma unroll
            for (int k = 0; k < 3; ++k)
#pragma unroll
                for (int p = 0; p < 8; ++p)
                    red[ty * 192 + k * 64 + 8 * tx + p] +=
                        red[(ty + s) * 192 + k * 64 + 8 * tx + p];
        }
        __syncthreads();
    }
}

// ================= K1 =================
__global__ __launch_bounds__(256) void k_gemm_mask(
    const float* __restrict__ F, const float* __restrict__ W1, const float* __restrict__ b1,
    const float* __restrict__ gg, const float* __restrict__ be, const float* __restrict__ mm,
    const float* __restrict__ vv, const float* __restrict__ W2, const float* __restrict__ b2,
    float* __restrict__ out) {
    extern __shared__ float sm[];
    float* fsm  = sm + SM_FSM;
    float* w2sm = sm + SM_W2;
    float* b2sm = sm + SM_B2;

    int b = blockIdx.y, n0 = blockIdx.x * TPTS, tid = threadIdx.x;
    int tx = tid & 7, ty = tid >> 3;

    for (int t = tid; t < 768; t += 256) w2sm[t] = W2[t];   // FIX: full 3x256 head
    if (tid < 3) b2sm[tid] = b2[tid];

    float sc[8], bias2[8], b1v[8];
    bn_params(gg, be, mm, vv, b1, ty, sc, bias2, b1v);

    const float* Fb = F + (size_t)b * Cc * Np;
    for (int idx = tid; idx < 256 * TPTS; idx += 256) {
        int c = idx >> 6, p = idx & 63;
        int n = n0 + p;
        fsm[idx] = (n < Np) ? Fb[(size_t)c * Np + n] : 0.f;
    }
    __syncthreads();

    float acc[8][8];
#pragma unroll
    for (int j = 0; j < 8; ++j)
#pragma unroll
        for (int p = 0; p < 8; ++p) acc[j][p] = 0.f;

    gemm_tile(W1, sm, tid, tx, ty, acc);

    float p3[3][8];
#pragma unroll
    for (int k = 0; k < 3; ++k)
#pragma unroll
        for (int p = 0; p < 8; ++p) p3[k][p] = 0.f;
    head3(w2sm, acc, sc, bias2, b1v, ty, p3);

    float* red = fsm;
    reduce3(red, p3, tx, ty);

    if (ty == 0) {
#pragma unroll
        for (int p = 0; p < 8; ++p) {
            int pt = 8 * tx + p;
            int n = n0 + pt;
            if (n < Np) {
                float s0 = __fadd_rn(red[pt], b2sm[0]);
                float s1 = __fadd_rn(red[64 + pt], b2sm[1]);
                float gr = __fadd_rn(red[128 + pt], b2sm[2]);
                out[OFF0 + (size_t)b * 2 * Np + n] = s0;
                out[OFF0 + (size_t)b * 2 * Np + Np + n] = s1;
                out[OFF1 + (size_t)b * Np + n] = gr;
                g_mask[b * Np + n] = (unsigned char)((s1 > s0) && (gr > 0.1f));
            }
        }
    }
}

// ================= K3: compaction + masked FPS =================
__device__ __forceinline__ void cmb(float& v, int& i, float v2, int i2) {
    if (v2 > v || (v2 == v && i2 < i)) { v = v2; i = i2; }
}

__global__ __launch_bounds__(1024, 1) void k_fps(const float* __restrict__ xyz,
                                                 float* __restrict__ out) {
    extern __shared__ char smc[];
    float* dist  = (float*)smc;
    int*   seq   = (int*)(smc + 80000);
    float* rv    = (float*)(smc + 84096);
    int*   ri    = (int*)(smc + 84224);
    int*   wcnt  = (int*)(smc + 84352);
    float* bc    = (float*)(smc + 84480);
    int*   sBase = (int*)(smc + 84496);

    int b = blockIdx.x, tid = threadIdx.x, lane = tid & 31, wid = tid >> 5;
    const float* xb = xyz + (size_t)b * Np * 3;

    if (tid == 0) sBase[0] = 0;
    __syncthreads();

    for (int c0 = 0; c0 < Np; c0 += 1024) {
        int n = c0 + tid;
        bool mk = (n < Np) && g_mask[b * Np + n];
        unsigned bal = __ballot_sync(0xffffffffu, mk);
        int pre = __popc(bal & ((1u << lane) - 1u));
        if (lane == 0) wcnt[wid] = __popc(bal);
        __syncthreads();
        if (tid == 0) {
            int a = sBase[0];
            for (int w = 0; w < 32; ++w) { int t = wcnt[w]; wcnt[w] = a; a += t; }
            sBase[0] = a;
        }
        __syncthreads();
        if (mk) {
            int pos = wcnt[wid] + pre;
            g_cidx[b][pos] = n;
            g_cxyz[b][pos] = make_float4(xb[n * 3], xb[n * 3 + 1], xb[n * 3 + 2], 0.f);
        }
        __syncthreads();
    }
    int M = sBase[0];

    for (int i = tid; i < M; i += 1024) dist[i] = 1e10f;
    if (tid == 0) {
        seq[0] = 0;
        if (M > 0) { float4 p = g_cxyz[b][0]; bc[0] = p.x; bc[1] = p.y; bc[2] = p.z; }
    }
    __syncthreads();

    const float NEGINF = __int_as_float(0xff800000);
    if (M > 0) {
        const float4* cz = g_cxyz[b];
        for (int s = 1; s < NS; ++s) {
            float px = bc[0], py = bc[1], pz = bc[2];
            float best = NEGINF;
            int bi = 0x7fffffff;
            for (int i = tid; i < M; i += 1024) {
                float4 p = cz[i];
                float dx = __fsub_rn(p.x, px);
                float dy = __fsub_rn(p.y, py);
                float dz = __fsub_rn(p.z, pz);
                float d = __fadd_rn(__fadd_rn(__fmul_rn(dx, dx), __fmul_rn(dy, dy)),
                                    __fmul_rn(dz, dz));
                float nd = fminf(dist[i], d);
                dist[i] = nd;
                if (nd > best) { best = nd; bi = i; }
            }
#pragma unroll
            for (int o = 16; o > 0; o >>= 1) {
                float v2 = __shfl_down_sync(0xffffffffu, best, o);
                int j2 = __shfl_down_sync(0xffffffffu, bi, o);
                cmb(best, bi, v2, j2);
            }
            if (lane == 0) { rv[wid] = best; ri[wid] = bi; }
            __syncthreads();
            if (wid == 0) {
                best = rv[lane]; bi = ri[lane];
#pragma unroll
                for (int o = 16; o > 0; o >>= 1) {
                    float v2 = __shfl_down_sync(0xffffffffu, best, o);
                    int j2 = __shfl_down_sync(0xffffffffu, bi, o);
                    cmb(best, bi, v2, j2);
                }
                if (lane == 0) {
                    seq[s] = bi;
                    float4 p = cz[bi];
                    bc[0] = p.x; bc[1] = p.y; bc[2] = p.z;
                }
            }
            __syncthreads();
        }
    }

    {
        int orig; float x, y, z;
        if (M > 0) {
            int c = seq[tid];
            orig = g_cidx[b][c];
            float4 p = g_cxyz[b][c];
            x = p.x; y = p.y; z = p.z;
        } else {
            orig = 0; x = xb[0]; y = xb[1]; z = xb[2];
        }
        out[OFF3 + (size_t)b * NS + tid] = (float)orig;
        out[OFF2 + (size_t)b * NS * 3 + tid * 3 + 0] = x;
        out[OFF2 + (size_t)b * NS * 3 + tid * 3 + 1] = y;
        out[OFF2 + (size_t)b * NS * 3 + tid * 3 + 2] = z;
        out[OFF5 + (size_t)b * NS + tid] = out[OFF1 + (size_t)b * Np + orig];
        g_sel[b][tid] = orig;
    }
}

// ================= K4 =================
__global__ __launch_bounds__(256) void k_view(
    const float* __restrict__ F, const float* __restrict__ W1, const float* __restrict__ b1,
    const float* __restrict__ gg, const float* __restrict__ be, const float* __restrict__ mm,
    const float* __restrict__ vv, const float* __restrict__ W2, const float* __restrict__ b2,
    float* __restrict__ out) {
    extern __shared__ float sm[];
    float* fsm  = sm + SM_FSM;
    float* w2sm = sm + SM_W2;
    float* b2sm = sm + SM_B2;
    float* vsm  = sm + SM_VSM;
    int*   idxs = (int*)(sm + SM_IDX);
    float* vps  = sm + SM_VPS;

    int b = blockIdx.y, s0 = blockIdx.x * TPTS, tid = threadIdx.x;
    int tx = tid & 7, ty = tid >> 3;

    if (tid < TPTS) idxs[tid] = g_sel[b][s0 + tid];
    for (int t = tid; t < 768; t += 256) w2sm[t] = W2[t];   // FIX: full 3x256 head
    if (tid < 3) b2sm[tid] = b2[tid];

    for (int i = tid; i < NV; i += 256) {
        double z = (2.0 * (double)i + 1.0) / (double)NV - 1.0;
        double r = sqrt(fmax(1.0 - z * z, 0.0));
        double phi = (sqrt(5.0) - 1.0) / 2.0;
        double ang = (2.0 * 3.14159265358979323846) * (double)i * phi;
        float x = (float)(r * cos(ang)), y = (float)(r * sin(ang)), zf = (float)z;
        float nr2 = __fadd_rn(__fadd_rn(__fmul_rn(x, x), __fmul_rn(y, y)), __fmul_rn(zf, zf));
        float nr = fmaxf(sqrtf(nr2), 1e-8f);
        vsm[i * 3 + 0] = __fdiv_rn(x, nr);
        vsm[i * 3 + 1] = __fdiv_rn(y, nr);
        vsm[i * 3 + 2] = __fdiv_rn(zf, nr);
    }

    float sc[8], bias2[8], b1v[8];
    bn_params(gg, be, mm, vv, b1, ty, sc, bias2, b1v);
    __syncthreads();

    const float* Fb = F + (size_t)b * Cc * Np;
    for (int idx = tid; idx < 256 * TPTS; idx += 256) {
        int c = idx >> 6, s = idx & 63;
        float val = Fb[(size_t)c * Np + idxs[s]];
        fsm[idx] = val;
        out[OFF4 + (size_t)b * Cc * NS + (size_t)c * NS + s0 + s] = val;
    }
    __syncthreads();

    float acc[8][8];
#pragma unroll
    for (int j = 0; j < 8; ++j)
#pragma unroll
        for (int p = 0; p < 8; ++p) acc[j][p] = 0.f;

    gemm_tile(W1, sm, tid, tx, ty, acc);

    float p3[3][8];
#pragma unroll
    for (int k = 0; k < 3; ++k)
#pragma unroll
        for (int p = 0; p < 8; ++p) p3[k][p] = 0.f;
    head3(w2sm, acc, sc, bias2, b1v, ty, p3);

    float* red = fsm;
    reduce3(red, p3, tx, ty);

    if (ty == 0) {
#pragma unroll
        for (int p = 0; p < 8; ++p) {
            int pt = 8 * tx + p;
            int s = s0 + pt;
            float v0 = __fadd_rn(red[pt], b2sm[0]);
            float v1 = __fadd_rn(red[64 + pt], b2sm[1]);
            float v2 = __fadd_rn(red[128 + pt], b2sm[2]);
            out[OFF6 + (size_t)b * NS * 3 + (size_t)s * 3 + 0] = v0;
            out[OFF6 + (size_t)b * NS * 3 + (size_t)s * 3 + 1] = v1;
            out[OFF6 + (size_t)b * NS * 3 + (size_t)s * 3 + 2] = v2;
            vps[pt * 3 + 0] = v0; vps[pt * 3 + 1] = v1; vps[pt * 3 + 2] = v2;
        }
    }
    __syncthreads();

    if (tid < TPTS) {
        int s = s0 + tid;
        float vx = vps[tid * 3], vy = vps[tid * 3 + 1], vz = vps[tid * 3 + 2];
        float n2 = __fadd_rn(__fadd_rn(__fmul_rn(vx, vx), __fmul_rn(vy, vy)), __fmul_rn(vz, vz));
        float nr = fmaxf(sqrtf(n2), 1e-8f);
        float ax_ = __fdiv_rn(vx, nr), ay_ = __fdiv_rn(vy, nr), az_ = __fdiv_rn(vz, nr);
        float best = __int_as_float(0xff800000);
        int bi = 0;
        for (int v = 0; v < NV; ++v) {
            float c = __fadd_rn(__fadd_rn(__fmul_rn(ax_, vsm[v * 3]),
                                          __fmul_rn(ay_, vsm[v * 3 + 1])),
                                __fmul_rn(az_, vsm[v * 3 + 2]));
            if (c > best) { best = c; bi = v; }
        }
        out[OFF7 + (size_t)b * NS + s] = (float)bi;

        float tx0 = -vx, tx1 = -vy, tx2 = -vz;
        float ay0 = -tx1, ay1 = tx0, ay2 = 0.f;
        float s2 = ay0 * ay0 + ay1 * ay1;
        if (s2 == 0.f) { ay0 = 0.f; ay1 = 1.f; ay2 = 0.f; }
        float an = sqrtf(tx0 * tx0 + tx1 * tx1 + tx2 * tx2);
        float nx0 = tx0 / an, nx1 = tx1 / an, nx2 = tx2 / an;
        float bn = sqrtf(ay0 * ay0 + ay1 * ay1 + ay2 * ay2);
        float ny0 = ay0 / bn, ny1 = ay1 / bn, ny2 = ay2 / bn;
        float nz0 = nx1 * ny2 - nx2 * ny1;
        float nz1 = nx2 * ny0 - nx0 * ny2;
        float nz2 = nx0 * ny1 - nx1 * ny0;
        size_t base = OFF8 + ((size_t)b * NS + s) * 9;
        out[base + 0] = nx0; out[base + 1] = ny0; out[base + 2] = nz0;
        out[base + 3] = nx1; out[base + 4] = ny1; out[base + 5] = nz1;
        out[base + 6] = nx2; out[base + 7] = ny2; out[base + 8] = nz2;
    }
}

// ================= launch (robust input-order detection) =================
extern "C" void kernel_launch(void* const* d_in, const int* in_sizes, int n_in,
                              void* d_out, int out_size) {
    const float *xyz, *F, *w1, *b1, *gg, *be, *mm, *vv, *w2, *b2;
    const float *c1w, *c1b, *bng, *bnb, *bnm, *bnv, *c2w, *c2b;

    // seed_features is uniquely the largest input; its position identifies the order
    // regardless of whether sizes are reported in elements or bytes.
    int imax = 0;
    for (int i = 1; i < n_in; ++i)
        if (in_sizes[i] > in_sizes[imax]) imax = i;

    if (imax == 1) {  // dict-insertion / signature order
        xyz = (const float*)d_in[0];  F   = (const float*)d_in[1];
        w1  = (const float*)d_in[2];  b1  = (const float*)d_in[3];
        gg  = (const float*)d_in[4];  be  = (const float*)d_in[5];
        mm  = (const float*)d_in[6];  vv  = (const float*)d_in[7];
        w2  = (const float*)d_in[8];  b2  = (const float*)d_in[9];
        c1w = (const float*)d_in[10]; c1b = (const float*)d_in[11];
        bng = (const float*)d_in[12]; bnb = (const float*)d_in[13];
        bnm = (const float*)d_in[14]; bnv = (const float*)d_in[15];
        c2w = (const float*)d_in[16]; c2b = (const float*)d_in[17];
    } else {          // alphabetical order (seed_features at 16)
        bnb = (const float*)d_in[0];  bng = (const float*)d_in[1];
        bnm = (const float*)d_in[2];  bnv = (const float*)d_in[3];
        c1b = (const float*)d_in[4];  c1w = (const float*)d_in[5];
        c2b = (const float*)d_in[6];  c2w = (const float*)d_in[7];
        b1  = (const float*)d_in[8];  b2  = (const float*)d_in[9];
        be  = (const float*)d_in[10]; gg  = (const float*)d_in[11];
        mm  = (const float*)d_in[12]; vv  = (const float*)d_in[13];
        w1  = (const float*)d_in[14]; w2  = (const float*)d_in[15];
        F   = (const float*)d_in[16]; xyz = (const float*)d_in[17];
    }
    float* out = (float*)d_out;

    const int SM1 = SM1_FLOATS * 4;
    const int SM3 = 84608;
    const int SM4 = SM4_FLOATS * 4;
    cudaFuncSetAttribute(k_gemm_mask, cudaFuncAttributeMaxDynamicSharedMemorySize, SM1);
    cudaFuncSetAttribute(k_fps, cudaFuncAttributeMaxDynamicSharedMemorySize, SM3);
    cudaFuncSetAttribute(k_view, cudaFuncAttributeMaxDynamicSharedMemorySize, SM4);

    dim3 g1((Np + TPTS - 1) / TPTS, Bb);
    k_gemm_mask<<<g1, 256, SM1>>>(F, w1, b1, gg, be, mm, vv, w2, b2, out);
    k_fps<<<Bb, 1024, SM3>>>(xyz, out);
    dim3 g4(NS / TPTS, Bb);
    k_view<<<g4, 256, SM4>>>(F, c1w, c1b, bng, bnb, bnm, bnv, c2w, c2b, out);
}